// round 16
// baseline (speedup 1.0000x reference)
#include <cuda_runtime.h>
#include <cuda_bf16.h>
#include <cstdint>

#define B_  16
#define C_  512
#define HW_ 4096

// ---------------- scratch (static device globals: alloc-free) ----------------
__device__ float g_Ws[(size_t)B_ * C_ * C_];                 // 16.8 MB fp32
__device__ __nv_bfloat16 g_xb[(size_t)B_ * C_ * HW_];        // 67 MB bf16 copy of x
__device__ float g_v[2][B_ * C_];
__device__ float g_u[B_ * HW_];
__device__ float g_unorm[B_];
__device__ unsigned g_bar_count;
__device__ volatile unsigned g_bar_gen;

__device__ __forceinline__ uint32_t smem_u32(const void* p) {
    uint32_t a;
    asm("{ .reg .u64 t; cvta.to.shared.u64 t, %1; cvt.u32.u64 %0, t; }" : "=r"(a) : "l"(p));
    return a;
}

// ---------------- x -> bf16 ----------------
__global__ void to_bf16(const float* __restrict__ x) {
    size_t i = ((size_t)blockIdx.x * 256 + threadIdx.x) * 8;
    float4 a = *(const float4*)&x[i];
    float4 c = *(const float4*)&x[i + 4];
    __nv_bfloat162* o = (__nv_bfloat162*)&g_xb[i];
    o[0] = __floats2bfloat162_rn(a.x, a.y);
    o[1] = __floats2bfloat162_rn(a.z, a.w);
    o[2] = __floats2bfloat162_rn(c.x, c.y);
    o[3] = __floats2bfloat162_rn(c.z, c.w);
}

// ---------------- HMMA GEMM: Ws[b] = Xb Xb^T (upper-tri tiles only) ----------
__device__ __forceinline__ void tile_pair(int t, int& tm, int& tn) {
    if (t < 4)      { tm = 0; tn = t; }
    else if (t < 7) { tm = 1; tn = t - 3; }
    else if (t < 9) { tm = 2; tn = t - 5; }
    else            { tm = 3; tn = 3; }
}

#define BKH 32
#define LDA 40        // padded row length (bf16 elems): 80B rows, conflict-free ldmatrix
#define GSTAGES 3
#define GEMM_SMEM (GSTAGES * 2 * 128 * LDA * 2)   // 61440 B

__global__ void __launch_bounds__(256, 1) gemm_ws_mma() {
    extern __shared__ __nv_bfloat16 smemb[];
    __nv_bfloat16* As = smemb;                       // 3 stages x 128*LDA
    __nv_bfloat16* Bs = smemb + GSTAGES * 128 * LDA;

    int tm, tn;
    tile_pair(blockIdx.x, tm, tn);
    const int b = blockIdx.y;
    const __nv_bfloat16* __restrict__ Xb = g_xb + (size_t)b * C_ * HW_;
    float* __restrict__ Ws = g_Ws + (size_t)b * C_ * C_;
    const int c0 = tm * 128;
    const int d0 = tn * 128;

    const int tid = threadIdx.x;
    const int lane = tid & 31;
    const int warp = tid >> 5;
    const int wm = warp >> 2;       // 0..1  -> 64-row slab
    const int wn = warp & 3;        // 0..3  -> 32-col slab

    const uint32_t aBase = smem_u32(As);
    const uint32_t bBase = smem_u32(Bs);

    float acc[4][4][4];
    #pragma unroll
    for (int ma = 0; ma < 4; ma++)
        #pragma unroll
        for (int na = 0; na < 4; na++)
            #pragma unroll
            for (int q = 0; q < 4; q++) acc[ma][na][q] = 0.f;

    // stage load: 128 rows x 32 bf16 (4 x 16B per row) for A and B
    auto issue = [&](int s, int k0) {
        #pragma unroll
        for (int i = 0; i < 2; i++) {
            const int t = tid + i * 256;          // 0..511
            const int row = t >> 2;
            const int seg = t & 3;
            const uint32_t so = (uint32_t)(s * 128 * LDA + row * LDA + seg * 8) * 2;
            asm volatile("cp.async.cg.shared.global [%0], [%1], 16;"
                         :: "r"(aBase + so), "l"(Xb + (size_t)(c0 + row) * HW_ + k0 + seg * 8));
            asm volatile("cp.async.cg.shared.global [%0], [%1], 16;"
                         :: "r"(bBase + so), "l"(Xb + (size_t)(d0 + row) * HW_ + k0 + seg * 8));
        }
        asm volatile("cp.async.commit_group;");
    };

    const int NCHUNK = HW_ / BKH;                 // 128
    issue(0, 0);
    issue(1, BKH);
    for (int i = 0; i < NCHUNK; i++) {
        const int s = i % 3;
        if (i + 2 < NCHUNK) {
            issue((i + 2) % 3, (i + 2) * BKH);
            asm volatile("cp.async.wait_group 2;");
        } else if (i + 1 < NCHUNK) {
            asm volatile("cp.async.wait_group 1;");
        } else {
            asm volatile("cp.async.wait_group 0;");
        }
        __syncthreads();

        #pragma unroll
        for (int ks = 0; ks < 2; ks++) {          // two k16 steps per chunk
            uint32_t a[4][4], bbf[4][2];
            #pragma unroll
            for (int ma = 0; ma < 4; ma++) {
                const int row = wm * 64 + ma * 16 + (lane & 15);
                const uint32_t addr = aBase +
                    (uint32_t)(s * 128 * LDA + row * LDA + ks * 16 + (lane >> 4) * 8) * 2;
                asm volatile("ldmatrix.sync.aligned.m8n8.x4.shared.b16 {%0,%1,%2,%3}, [%4];"
                             : "=r"(a[ma][0]), "=r"(a[ma][1]), "=r"(a[ma][2]), "=r"(a[ma][3])
                             : "r"(addr));
            }
            #pragma unroll
            for (int na = 0; na < 4; na++) {
                const int row = wn * 32 + na * 8 + (lane & 7);
                const uint32_t addr = bBase +
                    (uint32_t)(s * 128 * LDA + row * LDA + ks * 16 + ((lane >> 3) & 1) * 8) * 2;
                asm volatile("ldmatrix.sync.aligned.m8n8.x2.shared.b16 {%0,%1}, [%2];"
                             : "=r"(bbf[na][0]), "=r"(bbf[na][1]) : "r"(addr));
            }
            #pragma unroll
            for (int ma = 0; ma < 4; ma++)
                #pragma unroll
                for (int na = 0; na < 4; na++)
                    asm volatile(
                        "mma.sync.aligned.m16n8k16.row.col.f32.bf16.bf16.f32 "
                        "{%0,%1,%2,%3}, {%4,%5,%6,%7}, {%8,%9}, {%0,%1,%2,%3};"
                        : "+f"(acc[ma][na][0]), "+f"(acc[ma][na][1]),
                          "+f"(acc[ma][na][2]), "+f"(acc[ma][na][3])
                        : "r"(a[ma][0]), "r"(a[ma][1]), "r"(a[ma][2]), "r"(a[ma][3]),
                          "r"(bbf[na][0]), "r"(bbf[na][1]));
        }
        __syncthreads();
    }

    // epilogue: register fragments straight to gmem (float2 per atom-row)
    #pragma unroll
    for (int ma = 0; ma < 4; ma++) {
        const int row = c0 + wm * 64 + ma * 16 + (lane >> 2);
        #pragma unroll
        for (int na = 0; na < 4; na++) {
            const int col = d0 + wn * 32 + na * 8 + (lane & 3) * 2;
            *(float2*)&Ws[(size_t)row * C_ + col] =
                make_float2(acc[ma][na][0], acc[ma][na][1]);
            *(float2*)&Ws[(size_t)(row + 8) * C_ + col] =
                make_float2(acc[ma][na][2], acc[ma][na][3]);
        }
    }
}

// ---------------- mirror upper -> lower triangle (6 off-diag tiles) ----------
__global__ void mirror_ws() {
    const int pm[6] = {0, 0, 0, 1, 1, 2};
    const int pn[6] = {1, 2, 3, 2, 3, 3};
    const int c0 = pm[blockIdx.x] * 128;
    const int d0 = pn[blockIdx.x] * 128;
    float* __restrict__ Ws = g_Ws + (size_t)blockIdx.y * C_ * C_;

    __shared__ float sm[32][129];
    for (int sl = 0; sl < 4; sl++) {
        for (int t = threadIdx.x; t < 1024; t += 256) {
            const int r = t >> 5, c4 = (t & 31) * 4;
            float4 v = *(const float4*)&Ws[(size_t)(c0 + sl * 32 + r) * C_ + d0 + c4];
            sm[r][c4 + 0] = v.x; sm[r][c4 + 1] = v.y;
            sm[r][c4 + 2] = v.z; sm[r][c4 + 3] = v.w;
        }
        __syncthreads();
        for (int t = threadIdx.x; t < 1024; t += 256) {
            const int rr = t >> 3, q = (t & 7) * 4;
            float4 v = make_float4(sm[q + 0][rr], sm[q + 1][rr], sm[q + 2][rr], sm[q + 3][rr]);
            *(float4*)&Ws[(size_t)(d0 + rr) * C_ + c0 + sl * 32 + q] = v;
        }
        __syncthreads();
    }
}

// ---------------- fused 10-step power iteration + final normalize -----------
#define PITER_CTAS 256   // 16 CTAs per batch; << one wave -> co-resident

__device__ __forceinline__ void grid_bar() {
    __threadfence();
    __syncthreads();
    if (threadIdx.x == 0) {
        const unsigned gen = g_bar_gen;
        if (atomicAdd(&g_bar_count, 1) == PITER_CTAS - 1) {
            g_bar_count = 0;
            __threadfence();
            g_bar_gen = gen + 1;
        } else {
            while (g_bar_gen == gen) __nanosleep(32);
        }
    }
    __syncthreads();
}

__global__ void __launch_bounds__(256, 4) piter_all(const float* __restrict__ v0) {
    const int cta  = blockIdx.x;
    const int b    = cta >> 4;                 // 16 CTAs per batch
    const int dblk = cta & 15;                 // 32 d-columns each
    const int lane = threadIdx.x & 31;
    const int ty   = threadIdx.x >> 5;         // 0..7
    const int d    = dblk * 32 + lane;
    __shared__ float vs[C_];
    __shared__ float part[8][32];
    const float* __restrict__ Wsb = g_Ws + (size_t)b * C_ * C_;

    #pragma unroll 1
    for (int it = 0; it < 10; it++) {
        // iteration it reads parity (it&1) [it=0: external v0], writes parity (it+1)&1
        const float* __restrict__ vin = (it == 0) ? (v0 + b * C_) : &g_v[it & 1][b * C_];
        for (int i = threadIdx.x; i < C_; i += 256) vs[i] = vin[i];
        __syncthreads();
        float acc = 0.f;
        #pragma unroll 16
        for (int cc = 0; cc < 64; cc++) {
            const int c = ty * 64 + cc;
            acc += Wsb[(size_t)c * C_ + d] * vs[c];
        }
        part[ty][lane] = acc;
        __syncthreads();
        if (ty == 0) {
            float s = 0.f;
            #pragma unroll
            for (int t = 0; t < 8; t++) s += part[t][lane];
            g_v[(it + 1) & 1][b * C_ + d] = s * 0.0001220703125f;  // *2^-13, direction-safe
        }
        grid_bar();
    }

    // final v lives in g_v[0] (it=9 wrote parity 0); one CTA per batch normalizes
    if (dblk == 0) {
        float* v = &g_v[0][b * C_];
        const int t = threadIdx.x;
        const float a0 = v[t], a1 = v[t + 256];
        float s = a0 * a0 + a1 * a1;
        #pragma unroll
        for (int o = 16; o; o >>= 1) s += __shfl_xor_sync(0xFFFFFFFFu, s, o);
        __shared__ float red[8];
        if (lane == 0) red[ty] = s;
        __syncthreads();
        __shared__ float inv;
        if (t == 0) {
            float tot = 0.f;
            #pragma unroll
            for (int i = 0; i < 8; i++) tot += red[i];
            inv = rsqrtf(tot);
            g_unorm[b] = 0.f;
        }
        __syncthreads();
        v[t] = a0 * inv;
        v[t + 256] = a1 * inv;
    }
}

// ---------------- u = X^T v (bf16 x), accumulate ||u||^2 ----------------
__global__ void compute_u(int par) {
    const int b = blockIdx.y;
    const int n2 = blockIdx.x * 256 + threadIdx.x;      // bf16x2 pair index

    __shared__ float vs[C_];
    for (int i = threadIdx.x; i < C_; i += 256) vs[i] = g_v[par][b * C_ + i];
    __syncthreads();

    const __nv_bfloat162* __restrict__ X2 =
        (const __nv_bfloat162*)(g_xb + (size_t)b * C_ * HW_);
    float ax = 0.f, ay = 0.f;
    #pragma unroll 8
    for (int c = 0; c < C_; c++) {
        float2 f = __bfloat1622float2(X2[(size_t)c * (HW_ / 2) + n2]);
        ax += f.x * vs[c];
        ay += f.y * vs[c];
    }
    const int n = n2 * 2;
    *(float2*)&g_u[b * HW_ + n] = make_float2(ax, ay);

    float s = ax * ax + ay * ay;
    #pragma unroll
    for (int o = 16; o; o >>= 1) s += __shfl_xor_sync(0xFFFFFFFFu, s, o);
    __shared__ float red[8];
    if ((threadIdx.x & 31) == 0) red[threadIdx.x >> 5] = s;
    __syncthreads();
    if (threadIdx.x == 0) {
        float tot = 0.f;
        #pragma unroll
        for (int i = 0; i < 8; i++) tot += red[i];
        atomicAdd(&g_unorm[b], tot);
    }
}

// ---------------- out = x + (u/||u||) v^T ----------------
__global__ void fuse_out(const float* __restrict__ x, float* __restrict__ out, int par) {
    const size_t idx4 = (size_t)blockIdx.x * 256 + threadIdx.x;
    const size_t base = idx4 * 4;
    const int b = (int)(base >> 21);
    const int c = (int)((base >> 12) & 511);
    const int n = (int)(base & 4095);

    const float inv = rsqrtf(g_unorm[b]);
    const float vc  = g_v[par][b * C_ + c] * inv;

    float4 xv = *(const float4*)&x[base];
    float4 uu = *(const float4*)&g_u[b * HW_ + n];
    float4 o;
    o.x = xv.x + uu.x * vc;
    o.y = xv.y + uu.y * vc;
    o.z = xv.z + uu.z * vc;
    o.w = xv.w + uu.w * vc;
    *(float4*)&out[base] = o;
}

// ---------------- launch ----------------
extern "C" void kernel_launch(void* const* d_in, const int* in_sizes, int n_in,
                              void* d_out, int out_size) {
    (void)in_sizes; (void)n_in; (void)out_size;
    const float* x = (const float*)d_in[0];
    const float* v = (const float*)d_in[1];
    float* out = (float*)d_out;

    cudaFuncSetAttribute(gemm_ws_mma, cudaFuncAttributeMaxDynamicSharedMemorySize, GEMM_SMEM);

    to_bf16<<<(B_ * C_ * HW_) / (8 * 256), 256>>>(x);
    gemm_ws_mma<<<dim3(10, B_), 256, GEMM_SMEM>>>();
    mirror_ws<<<dim3(6, B_), 256>>>();

    piter_all<<<PITER_CTAS, 256>>>(v);

    compute_u<<<dim3(HW_ / 512, B_), 256>>>(0);
    fuse_out<<<(B_ * C_ * HW_) / (4 * 256), 256>>>(x, out, 0);
}